// round 2
// baseline (speedup 1.0000x reference)
#include <cuda_runtime.h>

#define B_  2
#define L_  4096
#define D_  1024
#define H_  16
#define DH_ 64
#define W_  512
#define C_  8
#define M_  (B_ * L_)   // 8192 rows total

// Scratch buffers (device globals: allocation-free per harness rules)
__device__ float g_q[M_ * D_];
__device__ float g_k[M_ * D_];
__device__ float g_v[M_ * D_];
__device__ float g_attn[M_ * D_];

// ---------------------------------------------------------------------------
// Tiled fp32 GEMM: C[m][n] = sum_k A[m][k] * Bw[n][k] + bias[n]
// BM=BN=128, BK=8, 256 threads, 8x8 per-thread tile, float4 everywhere.
// ---------------------------------------------------------------------------
__device__ __forceinline__ void gemm_body(const float* __restrict__ A,
                                          const float* __restrict__ Bw,
                                          const float* __restrict__ bias,
                                          float* __restrict__ C) {
    __shared__ float As[8][128];
    __shared__ float Bs[8][128];
    const int tid  = threadIdx.x;
    const int bm   = blockIdx.y * 128;
    const int bn   = blockIdx.x * 128;
    const int trow = (tid >> 4) << 3;   // 0..120 step 8
    const int tcol = (tid & 15) << 3;
    const int lrow = tid >> 1;          // 0..127
    const int lcol = (tid & 1) << 2;    // 0 or 4

    const float* Ap = A  + (size_t)(bm + lrow) * D_ + lcol;
    const float* Bp = Bw + (size_t)(bn + lrow) * D_ + lcol;

    float acc[8][8];
#pragma unroll
    for (int i = 0; i < 8; i++)
#pragma unroll
        for (int j = 0; j < 8; j++) acc[i][j] = 0.f;

    for (int k0 = 0; k0 < D_; k0 += 8) {
        float4 a4 = *(const float4*)(Ap + k0);
        float4 b4 = *(const float4*)(Bp + k0);
        As[lcol + 0][lrow] = a4.x;
        As[lcol + 1][lrow] = a4.y;
        As[lcol + 2][lrow] = a4.z;
        As[lcol + 3][lrow] = a4.w;
        Bs[lcol + 0][lrow] = b4.x;
        Bs[lcol + 1][lrow] = b4.y;
        Bs[lcol + 2][lrow] = b4.z;
        Bs[lcol + 3][lrow] = b4.w;
        __syncthreads();
#pragma unroll
        for (int kk = 0; kk < 8; kk++) {
            float ar[8], br[8];
            *(float4*)&ar[0] = *(const float4*)&As[kk][trow];
            *(float4*)&ar[4] = *(const float4*)&As[kk][trow + 4];
            *(float4*)&br[0] = *(const float4*)&Bs[kk][tcol];
            *(float4*)&br[4] = *(const float4*)&Bs[kk][tcol + 4];
#pragma unroll
            for (int i = 0; i < 8; i++)
#pragma unroll
                for (int j = 0; j < 8; j++)
                    acc[i][j] = fmaf(ar[i], br[j], acc[i][j]);
        }
        __syncthreads();
    }

#pragma unroll
    for (int i = 0; i < 8; i++) {
#pragma unroll
        for (int j = 0; j < 8; j += 4) {
            float4 o;
            o.x = acc[i][j + 0] + bias[bn + tcol + j + 0];
            o.y = acc[i][j + 1] + bias[bn + tcol + j + 1];
            o.z = acc[i][j + 2] + bias[bn + tcol + j + 2];
            o.w = acc[i][j + 3] + bias[bn + tcol + j + 3];
            *(float4*)&C[(size_t)(bm + trow + i) * D_ + bn + tcol + j] = o;
        }
    }
}

__global__ __launch_bounds__(256) void gemm_qkv_kernel(
    const float* __restrict__ x,
    const float* __restrict__ Wq, const float* __restrict__ bq,
    const float* __restrict__ Wk, const float* __restrict__ bk,
    const float* __restrict__ Wv, const float* __restrict__ bv) {
    const float* Wt;
    const float* bias;
    float* C;
    if (blockIdx.z == 0)      { Wt = Wq; bias = bq; C = g_q; }
    else if (blockIdx.z == 1) { Wt = Wk; bias = bk; C = g_k; }
    else                      { Wt = Wv; bias = bv; C = g_v; }
    gemm_body(x, Wt, bias, C);
}

__global__ __launch_bounds__(256) void gemm_out_kernel(
    const float* __restrict__ Wo, const float* __restrict__ bo,
    float* __restrict__ out) {
    gemm_body(g_attn, Wo, bo, out);
}

// ---------------------------------------------------------------------------
// Sliding-window flash attention.
// Block = (q-tile of 64 rows, head h, batch*chunk). 256 threads, 4x4/thread.
// Keys for chunk c are global rows [(c-1)*W, (c+1)*W); c==0 skips the first
// 8 key tiles (pure padding == the -1e9 mask in the reference).
// Q and K stored d-major in smem (conflict-free float4 reads); P (post-softmax)
// aliases the K buffer, transposed key-major for the PV stage.
// ---------------------------------------------------------------------------
__global__ __launch_bounds__(256) void attn_kernel() {
    __shared__ float QsT[64][64];   // [d][row]
    __shared__ float KPs[64][64];   // K: [d][key]   then P: [key][row]
    __shared__ float Vs[64][64];    // [key][d]

    const int tid = threadIdx.x;
    const int qt  = blockIdx.x;          // 0..7 (query tile within chunk)
    const int h   = blockIdx.y;          // 0..15
    const int b   = blockIdx.z >> 3;
    const int c   = blockIdx.z & 7;
    const int tx  = tid & 15;            // key / d column group
    const int ty  = tid >> 4;            // query row group
    const int lr  = tid >> 2;            // loader row 0..63
    const int ld  = (tid & 3) << 4;      // loader d base 0,16,32,48

    // Load Q tile (scale 1/sqrt(64) folded in), transposed to d-major.
    {
        const size_t qbase =
            ((size_t)(b * L_ + c * W_ + qt * 64 + lr)) * D_ + h * DH_ + ld;
#pragma unroll
        for (int u = 0; u < 4; u++) {
            float4 qv = *(const float4*)&g_q[qbase + u * 4];
            QsT[ld + u * 4 + 0][lr] = qv.x * 0.125f;
            QsT[ld + u * 4 + 1][lr] = qv.y * 0.125f;
            QsT[ld + u * 4 + 2][lr] = qv.z * 0.125f;
            QsT[ld + u * 4 + 3][lr] = qv.w * 0.125f;
        }
    }

    float m[4], l[4], o[4][4];
#pragma unroll
    for (int i = 0; i < 4; i++) {
        m[i] = -1e30f;
        l[i] = 0.f;
#pragma unroll
        for (int j = 0; j < 4; j++) o[i][j] = 0.f;
    }

    const int kt0 = (c == 0) ? 8 : 0;
    for (int kt = kt0; kt < 16; kt++) {
        __syncthreads();  // prev PV done (and Q visible on first iter)
        {
            const int krow = (c - 1) * W_ + kt * 64 + lr;
            const size_t kbase = ((size_t)(b * L_ + krow)) * D_ + h * DH_ + ld;
#pragma unroll
            for (int u = 0; u < 4; u++) {
                float4 kv = *(const float4*)&g_k[kbase + u * 4];
                KPs[ld + u * 4 + 0][lr] = kv.x;
                KPs[ld + u * 4 + 1][lr] = kv.y;
                KPs[ld + u * 4 + 2][lr] = kv.z;
                KPs[ld + u * 4 + 3][lr] = kv.w;
                *(float4*)&Vs[lr][ld + u * 4] = *(const float4*)&g_v[kbase + u * 4];
            }
        }
        __syncthreads();

        // S = (Q * scale) @ K^T  — 64x64 tile, 4x4 per thread
        float s[4][4];
#pragma unroll
        for (int i = 0; i < 4; i++)
#pragma unroll
            for (int j = 0; j < 4; j++) s[i][j] = 0.f;

#pragma unroll 8
        for (int dd = 0; dd < 64; dd++) {
            float qa[4], kb[4];
            *(float4*)qa = *(const float4*)&QsT[dd][ty << 2];
            *(float4*)kb = *(const float4*)&KPs[dd][tx << 2];
#pragma unroll
            for (int i = 0; i < 4; i++)
#pragma unroll
                for (int j = 0; j < 4; j++)
                    s[i][j] = fmaf(qa[i], kb[j], s[i][j]);
        }

        // Online softmax. Row group = 16 tx-threads = one half-warp.
#pragma unroll
        for (int i = 0; i < 4; i++) {
            float mx = fmaxf(fmaxf(s[i][0], s[i][1]), fmaxf(s[i][2], s[i][3]));
            mx = fmaxf(mx, __shfl_xor_sync(0xffffffffu, mx, 1));
            mx = fmaxf(mx, __shfl_xor_sync(0xffffffffu, mx, 2));
            mx = fmaxf(mx, __shfl_xor_sync(0xffffffffu, mx, 4));
            mx = fmaxf(mx, __shfl_xor_sync(0xffffffffu, mx, 8));
            float mnew = fmaxf(m[i], mx);
            float corr = __expf(m[i] - mnew);
            float rs = 0.f;
#pragma unroll
            for (int j = 0; j < 4; j++) {
                s[i][j] = __expf(s[i][j] - mnew);
                rs += s[i][j];
            }
            rs += __shfl_xor_sync(0xffffffffu, rs, 1);
            rs += __shfl_xor_sync(0xffffffffu, rs, 2);
            rs += __shfl_xor_sync(0xffffffffu, rs, 4);
            rs += __shfl_xor_sync(0xffffffffu, rs, 8);
            l[i] = l[i] * corr + rs;
            m[i] = mnew;
#pragma unroll
            for (int j = 0; j < 4; j++) o[i][j] *= corr;
        }

        __syncthreads();  // all threads done reading KPs as K
        // Store P transposed (key-major) into the K buffer.
#pragma unroll
        for (int i = 0; i < 4; i++)
#pragma unroll
            for (int j = 0; j < 4; j++)
                KPs[(tx << 2) + j][(ty << 2) + i] = s[i][j];
        __syncthreads();

        // O += P @ V
#pragma unroll 8
        for (int kk = 0; kk < 64; kk++) {
            float pa[4], vb[4];
            *(float4*)pa = *(const float4*)&KPs[kk][ty << 2];
            *(float4*)vb = *(const float4*)&Vs[kk][tx << 2];
#pragma unroll
            for (int i = 0; i < 4; i++)
#pragma unroll
                for (int j = 0; j < 4; j++)
                    o[i][j] = fmaf(pa[i], vb[j], o[i][j]);
        }
    }

    // Epilogue: normalize and write.
#pragma unroll
    for (int i = 0; i < 4; i++) {
        const float inv = 1.0f / l[i];
        const size_t obase =
            ((size_t)(b * L_ + c * W_ + qt * 64 + (ty << 2) + i)) * D_ +
            h * DH_ + (tx << 2);
        float4 ov;
        ov.x = o[i][0] * inv;
        ov.y = o[i][1] * inv;
        ov.z = o[i][2] * inv;
        ov.w = o[i][3] * inv;
        *(float4*)&g_attn[obase] = ov;
    }
}

// ---------------------------------------------------------------------------
extern "C" void kernel_launch(void* const* d_in, const int* in_sizes, int n_in,
                              void* d_out, int out_size) {
    const float* x  = (const float*)d_in[0];
    const float* Wq = (const float*)d_in[1];
    const float* bq = (const float*)d_in[2];
    const float* Wk = (const float*)d_in[3];
    const float* bk = (const float*)d_in[4];
    const float* Wv = (const float*)d_in[5];
    const float* bv = (const float*)d_in[6];
    const float* Wo = (const float*)d_in[7];
    const float* bo = (const float*)d_in[8];
    float* out = (float*)d_out;

    // QKV projections: one launch, z selects q/k/v
    dim3 gqkv(D_ / 128, M_ / 128, 3);
    gemm_qkv_kernel<<<gqkv, 256>>>(x, Wq, bq, Wk, bk, Wv, bv);

    // Sliding-window attention
    attn_kernel<<<dim3(W_ / 64, H_, B_ * C_), 256>>>();

    // Output projection -> d_out
    gemm_out_kernel<<<dim3(D_ / 128, M_ / 128), 256>>>(Wo, bo, out);
}

// round 7
// speedup vs baseline: 3.9291x; 3.9291x over previous
#include <cuda_runtime.h>
#include <cstdint>

#define B_  2
#define L_  4096
#define D_  1024
#define H_  16
#define W_  512
#define C_  8
#define M_  (B_ * L_)

// Scratch (device globals: allocation-free per harness rules)
__device__ float g_q[M_ * D_];
__device__ float g_k[M_ * D_];
__device__ float g_v[M_ * D_];
__device__ float g_attn[M_ * D_];

// ---------------------------------------------------------------------------
// helpers
// ---------------------------------------------------------------------------
__device__ __forceinline__ uint32_t f2tf(float x) {
    uint32_t r;
    asm("cvt.rna.tf32.f32 %0, %1;" : "=r"(r) : "f"(x));
    return r;
}
__device__ __forceinline__ float ex2(float x) {
    float y;
    asm("ex2.approx.ftz.f32 %0, %1;" : "=f"(y) : "f"(x));
    return y;
}
// D += A*B, m16n8k8 tf32. A row-major frag (4 regs), B col-major frag (2 regs).
__device__ __forceinline__ void mma8(float* d, const uint32_t* a, const uint32_t* b) {
    asm volatile(
        "mma.sync.aligned.m16n8k8.row.col.f32.tf32.tf32.f32 "
        "{%0,%1,%2,%3}, {%4,%5,%6,%7}, {%8,%9}, {%0,%1,%2,%3};"
        : "+f"(d[0]), "+f"(d[1]), "+f"(d[2]), "+f"(d[3])
        : "r"(a[0]), "r"(a[1]), "r"(a[2]), "r"(a[3]), "r"(b[0]), "r"(b[1]));
}

// ---------------------------------------------------------------------------
// tf32 mma.sync GEMM: C[m][n] = sum_k A[m][k]*Bw[n][k] + bias[n]
// 128 threads, 4 warps (2x2), warp tile 64x64, BK=32, reg-prefetched loads.
// smem stride 36 floats -> fragment LDS bank = (4g+t) mod 32, conflict-free.
// ---------------------------------------------------------------------------
__device__ __forceinline__ void gemm_body(const float* __restrict__ A,
                                          const float* __restrict__ Bw,
                                          const float* __restrict__ bias,
                                          float* __restrict__ Cout) {
    __shared__ float As[128][36];
    __shared__ float Bs[128][36];
    const int tid  = threadIdx.x;
    const int lane = tid & 31;
    const int warp = tid >> 5;
    const int g = lane >> 2, t = lane & 3;
    const int bm = blockIdx.y * 128;
    const int bn = blockIdx.x * 128;
    const int wm = (warp & 1) * 64;
    const int wn = (warp >> 1) * 64;

    float acc[4][8][4];
#pragma unroll
    for (int mi = 0; mi < 4; mi++)
#pragma unroll
        for (int nj = 0; nj < 8; nj++)
#pragma unroll
            for (int e = 0; e < 4; e++) acc[mi][nj][e] = 0.f;

    float4 pa[8], pb[8];
#define GEMM_LDG(j)                                                             \
    _Pragma("unroll")                                                           \
    for (int p = 0; p < 8; p++) {                                               \
        int s_ = tid + p * 128; int r_ = s_ >> 3, c4_ = s_ & 7;                 \
        pa[p] = *(const float4*)&A[(size_t)(bm + r_) * D_ + (j) * 32 + c4_ * 4];\
        pb[p] = *(const float4*)&Bw[(size_t)(bn + r_) * D_ + (j) * 32 + c4_ * 4];\
    }

    GEMM_LDG(0);
    for (int j = 0; j < 32; j++) {
        if (j) __syncthreads();
#pragma unroll
        for (int p = 0; p < 8; p++) {
            int s_ = tid + p * 128; int r_ = s_ >> 3, c4_ = s_ & 7;
            float4 a4 = pa[p];
            a4.x = __uint_as_float(f2tf(a4.x)); a4.y = __uint_as_float(f2tf(a4.y));
            a4.z = __uint_as_float(f2tf(a4.z)); a4.w = __uint_as_float(f2tf(a4.w));
            *(float4*)&As[r_][c4_ * 4] = a4;
            float4 b4 = pb[p];
            b4.x = __uint_as_float(f2tf(b4.x)); b4.y = __uint_as_float(f2tf(b4.y));
            b4.z = __uint_as_float(f2tf(b4.z)); b4.w = __uint_as_float(f2tf(b4.w));
            *(float4*)&Bs[r_][c4_ * 4] = b4;
        }
        __syncthreads();
        if (j + 1 < 32) { GEMM_LDG(j + 1); }

#pragma unroll
        for (int ks = 0; ks < 4; ks++) {
            uint32_t af[4][4];
#pragma unroll
            for (int mi = 0; mi < 4; mi++) {
                const int r0 = wm + mi * 16 + g, cc = ks * 8 + t;
                af[mi][0] = __float_as_uint(As[r0][cc]);
                af[mi][1] = __float_as_uint(As[r0 + 8][cc]);
                af[mi][2] = __float_as_uint(As[r0][cc + 4]);
                af[mi][3] = __float_as_uint(As[r0 + 8][cc + 4]);
            }
#pragma unroll
            for (int nj = 0; nj < 8; nj++) {
                uint32_t bf[2];
                const int rn = wn + nj * 8 + g, cc = ks * 8 + t;
                bf[0] = __float_as_uint(Bs[rn][cc]);
                bf[1] = __float_as_uint(Bs[rn][cc + 4]);
#pragma unroll
                for (int mi = 0; mi < 4; mi++) mma8(acc[mi][nj], af[mi], bf);
            }
        }
    }
#undef GEMM_LDG

    // Epilogue. C-frag: c0 (g,2t) c1 (g,2t+1) c2 (g+8,2t) c3 (g+8,2t+1)
#pragma unroll
    for (int mi = 0; mi < 4; mi++) {
#pragma unroll
        for (int nj = 0; nj < 8; nj++) {
            const int col = bn + wn + nj * 8 + 2 * t;
            const float bx = bias[col], by = bias[col + 1];
            const int r0 = bm + wm + mi * 16 + g;
            float2 v0 = { acc[mi][nj][0] + bx, acc[mi][nj][1] + by };
            float2 v1 = { acc[mi][nj][2] + bx, acc[mi][nj][3] + by };
            *(float2*)&Cout[(size_t)r0 * D_ + col] = v0;
            *(float2*)&Cout[(size_t)(r0 + 8) * D_ + col] = v1;
        }
    }
}

__global__ __launch_bounds__(128) void gemm_qkv_tc(
    const float* __restrict__ x,
    const float* __restrict__ Wq, const float* __restrict__ bq,
    const float* __restrict__ Wk, const float* __restrict__ bk,
    const float* __restrict__ Wv, const float* __restrict__ bv) {
    const float* Wt; const float* bias; float* C;
    if (blockIdx.z == 0)      { Wt = Wq; bias = bq; C = g_q; }
    else if (blockIdx.z == 1) { Wt = Wk; bias = bk; C = g_k; }
    else                      { Wt = Wv; bias = bv; C = g_v; }
    gemm_body(x, Wt, bias, C);
}

__global__ __launch_bounds__(128) void gemm_out_tc(
    const float* __restrict__ Wo, const float* __restrict__ bo,
    float* __restrict__ out) {
    gemm_body(g_attn, Wo, bo, out);
}

// ---------------------------------------------------------------------------
// Sliding-window flash attention on mma.sync tf32.
// 128 threads (4 warps), q-tile 128 rows, warp owns 32 rows (2 m-atoms).
// Q frags in regs (scale*log2e folded). K/V in smem, stride 72 floats
// (injective banks for both K^T b-frags and V b-frags).
// P C-frag -> A-frag via quad shuffles (no smem roundtrip).
// ---------------------------------------------------------------------------
__global__ __launch_bounds__(128) void attn_tc() {
    __shared__ float Ks[64][72];   // [key][d]
    __shared__ float Vs[64][72];   // [key][d]

    const int tid  = threadIdx.x;
    const int lane = tid & 31;
    const int warp = tid >> 5;
    const int g = lane >> 2, t = lane & 3;
    const int qt = blockIdx.x;            // 0..3 (128-row tile in chunk)
    const int h  = blockIdx.y;
    const int b  = blockIdx.z >> 3;
    const int c  = blockIdx.z & 7;
    const float qscale = 0.125f * 1.4426950408889634f;  // 1/sqrt(64) * log2e
    const int qrow0 = b * L_ + c * W_ + qt * 128 + warp * 32;

    // Q a-frags for the whole kernel: qf[mi][ks] = rows {g, g+8}, cols {t, t+4}
    uint32_t qf[2][8][4];
#pragma unroll
    for (int mi = 0; mi < 2; mi++)
#pragma unroll
        for (int ks = 0; ks < 8; ks++) {
            const int col = h * 64 + ks * 8 + t;
            const float* q0 = &g_q[(size_t)(qrow0 + mi * 16 + g) * D_ + col];
            const float* q8 = &g_q[(size_t)(qrow0 + mi * 16 + g + 8) * D_ + col];
            qf[mi][ks][0] = f2tf(q0[0] * qscale);
            qf[mi][ks][1] = f2tf(q8[0] * qscale);
            qf[mi][ks][2] = f2tf(q0[4] * qscale);
            qf[mi][ks][3] = f2tf(q8[4] * qscale);
        }

    float of[2][8][4];
    float mrow[4], lrow[4];
#pragma unroll
    for (int i = 0; i < 4; i++) { mrow[i] = -1e30f; lrow[i] = 0.f; }
#pragma unroll
    for (int mi = 0; mi < 2; mi++)
#pragma unroll
        for (int nj = 0; nj < 8; nj++)
#pragma unroll
            for (int e = 0; e < 4; e++) of[mi][nj][e] = 0.f;

    const int kt0 = (c == 0) ? 8 : 0;   // chunk 0 lookback is pure padding
    for (int kt = kt0; kt < 16; kt++) {
        __syncthreads();
        {
            const int tb = b * L_ + (c - 1) * W_ + kt * 64;
#pragma unroll
            for (int p = 0; p < 8; p++) {
                int s_ = tid + p * 128; int r_ = s_ >> 4, c4_ = s_ & 15;
                const size_t gb = (size_t)(tb + r_) * D_ + h * 64 + c4_ * 4;
                float4 kv = *(const float4*)&g_k[gb];
                kv.x = __uint_as_float(f2tf(kv.x)); kv.y = __uint_as_float(f2tf(kv.y));
                kv.z = __uint_as_float(f2tf(kv.z)); kv.w = __uint_as_float(f2tf(kv.w));
                *(float4*)&Ks[r_][c4_ * 4] = kv;
                float4 vv = *(const float4*)&g_v[gb];
                vv.x = __uint_as_float(f2tf(vv.x)); vv.y = __uint_as_float(f2tf(vv.y));
                vv.z = __uint_as_float(f2tf(vv.z)); vv.w = __uint_as_float(f2tf(vv.w));
                *(float4*)&Vs[r_][c4_ * 4] = vv;
            }
        }
        __syncthreads();

        // S = Q @ K^T  (b-frag: B(k=d,n=key) = Ks[key][d])
        float s[2][8][4];
#pragma unroll
        for (int mi = 0; mi < 2; mi++)
#pragma unroll
            for (int nj = 0; nj < 8; nj++)
#pragma unroll
                for (int e = 0; e < 4; e++) s[mi][nj][e] = 0.f;

#pragma unroll
        for (int ks = 0; ks < 8; ks++) {
#pragma unroll
            for (int nj = 0; nj < 8; nj++) {
                uint32_t bf[2];
                bf[0] = __float_as_uint(Ks[nj * 8 + g][ks * 8 + t]);
                bf[1] = __float_as_uint(Ks[nj * 8 + g][ks * 8 + t + 4]);
                mma8(s[0][nj], qf[0][ks], bf);
                mma8(s[1][nj], qf[1][ks], bf);
            }
        }

        // Online softmax (base-2 domain; row = quad of 4 lanes)
#pragma unroll
        for (int mi = 0; mi < 2; mi++) {
#pragma unroll
            for (int hh = 0; hh < 2; hh++) {
                const int e0 = hh * 2;
                float mx = -1e30f;
#pragma unroll
                for (int nj = 0; nj < 8; nj++)
                    mx = fmaxf(mx, fmaxf(s[mi][nj][e0], s[mi][nj][e0 + 1]));
                mx = fmaxf(mx, __shfl_xor_sync(0xffffffffu, mx, 1));
                mx = fmaxf(mx, __shfl_xor_sync(0xffffffffu, mx, 2));
                const int li = mi * 2 + hh;
                const float mnew = fmaxf(mrow[li], mx);
                const float corr = ex2(mrow[li] - mnew);
                float rs = 0.f;
#pragma unroll
                for (int nj = 0; nj < 8; nj++) {
                    float p0 = ex2(s[mi][nj][e0] - mnew);
                    float p1 = ex2(s[mi][nj][e0 + 1] - mnew);
                    s[mi][nj][e0] = p0; s[mi][nj][e0 + 1] = p1;
                    rs += p0 + p1;
                    of[mi][nj][e0] *= corr;
                    of[mi][nj][e0 + 1] *= corr;
                }
                rs += __shfl_xor_sync(0xffffffffu, rs, 1);
                rs += __shfl_xor_sync(0xffffffffu, rs, 2);
                lrow[li] = lrow[li] * corr + rs;
                mrow[li] = mnew;
            }
        }

        // O += P @ V. P C-frag -> A-frag via quad shuffles.
        const int qb = lane & 28;
        const int srcA = qb | (t >> 1);
        const int srcB = qb | ((t >> 1) + 2);
        const bool odd = (t & 1);
#pragma unroll
        for (int kk = 0; kk < 8; kk++) {
            uint32_t am[2][4];
#pragma unroll
            for (int mi = 0; mi < 2; mi++) {
                float x0 = __shfl_sync(0xffffffffu, s[mi][kk][0], srcA);
                float x1 = __shfl_sync(0xffffffffu, s[mi][kk][1], srcA);
                float x2 = __shfl_sync(0xffffffffu, s[mi][kk][2], srcA);
                float x3 = __shfl_sync(0xffffffffu, s[mi][kk][3], srcA);
                float y0 = __shfl_sync(0xffffffffu, s[mi][kk][0], srcB);
                float y1 = __shfl_sync(0xffffffffu, s[mi][kk][1], srcB);
                float y2 = __shfl_sync(0xffffffffu, s[mi][kk][2], srcB);
                float y3 = __shfl_sync(0xffffffffu, s[mi][kk][3], srcB);
                am[mi][0] = f2tf(odd ? x1 : x0);
                am[mi][1] = f2tf(odd ? x3 : x2);
                am[mi][2] = f2tf(odd ? y1 : y0);
                am[mi][3] = f2tf(odd ? y3 : y2);
            }
#pragma unroll
            for (int nj = 0; nj < 8; nj++) {
                uint32_t bf[2];
                bf[0] = __float_as_uint(Vs[kk * 8 + t][nj * 8 + g]);
                bf[1] = __float_as_uint(Vs[kk * 8 + t + 4][nj * 8 + g]);
                mma8(of[0][nj], am[0], bf);
                mma8(of[1][nj], am[1], bf);
            }
        }
    }

    // Epilogue: normalize and write
#pragma unroll
    for (int mi = 0; mi < 2; mi++) {
        const float inv0 = 1.f / lrow[mi * 2];
        const float inv1 = 1.f / lrow[mi * 2 + 1];
#pragma unroll
        for (int nj = 0; nj < 8; nj++) {
            const int col = h * 64 + nj * 8 + 2 * t;
            const int r0 = qrow0 + mi * 16 + g;
            float2 v0 = { of[mi][nj][0] * inv0, of[mi][nj][1] * inv0 };
            float2 v1 = { of[mi][nj][2] * inv1, of[mi][nj][3] * inv1 };
            *(float2*)&g_attn[(size_t)r0 * D_ + col] = v0;
            *(float2*)&g_attn[(size_t)(r0 + 8) * D_ + col] = v1;
        }
    }
}

// ---------------------------------------------------------------------------
extern "C" void kernel_launch(void* const* d_in, const int* in_sizes, int n_in,
                              void* d_out, int out_size) {
    const float* x  = (const float*)d_in[0];
    const float* Wq = (const float*)d_in[1];
    const float* bq = (const float*)d_in[2];
    const float* Wk = (const float*)d_in[3];
    const float* bk = (const float*)d_in[4];
    const float* Wv = (const float*)d_in[5];
    const float* bv = (const float*)d_in[6];
    const float* Wo = (const float*)d_in[7];
    const float* bo = (const float*)d_in[8];
    float* out = (float*)d_out;

    gemm_qkv_tc<<<dim3(D_ / 128, M_ / 128, 3), 128>>>(x, Wq, bq, Wk, bk, Wv, bv);
    attn_tc<<<dim3(4, H_, B_ * C_), 128>>>();
    gemm_out_tc<<<dim3(D_ / 128, M_ / 128), 128>>>(Wo, bo, out);
}

// round 8
// speedup vs baseline: 4.1538x; 1.0572x over previous
#include <cuda_runtime.h>
#include <cstdint>

#define B_  2
#define L_  4096
#define D_  1024
#define H_  16
#define W_  512
#define C_  8
#define M_  (B_ * L_)

// Scratch (device globals: allocation-free per harness rules)
__device__ float g_q[M_ * D_];
__device__ float g_k[M_ * D_];
__device__ float g_v[M_ * D_];
__device__ float g_attn[M_ * D_];
__device__ float g_xr[M_ * D_];        // x rounded to tf32
__device__ float g_wr[4 * D_ * D_];    // Wq,Wk,Wv,Wo rounded to tf32

// ---------------------------------------------------------------------------
// helpers
// ---------------------------------------------------------------------------
__device__ __forceinline__ uint32_t f2tf(float x) {
    uint32_t r;
    asm("cvt.rna.tf32.f32 %0, %1;" : "=r"(r) : "f"(x));
    return r;
}
__device__ __forceinline__ float ex2(float x) {
    float y;
    asm("ex2.approx.ftz.f32 %0, %1;" : "=f"(y) : "f"(x));
    return y;
}
__device__ __forceinline__ uint32_t smem_u32(const void* p) {
    uint32_t a;
    asm("{ .reg .u64 t; cvta.to.shared.u64 t, %1; cvt.u32.u64 %0, t; }"
        : "=r"(a) : "l"(p));
    return a;
}
__device__ __forceinline__ void cp_async16(uint32_t dst, const void* src) {
    asm volatile("cp.async.cg.shared.global [%0], [%1], 16;" :: "r"(dst), "l"(src));
}
#define CP_COMMIT()  asm volatile("cp.async.commit_group;" ::: "memory")
#define CP_WAIT(n)   asm volatile("cp.async.wait_group %0;" :: "n"(n) : "memory")

// D += A*B, m16n8k8 tf32
__device__ __forceinline__ void mma8(float* d, const uint32_t* a, const uint32_t* b) {
    asm volatile(
        "mma.sync.aligned.m16n8k8.row.col.f32.tf32.tf32.f32 "
        "{%0,%1,%2,%3}, {%4,%5,%6,%7}, {%8,%9}, {%0,%1,%2,%3};"
        : "+f"(d[0]), "+f"(d[1]), "+f"(d[2]), "+f"(d[3])
        : "r"(a[0]), "r"(a[1]), "r"(a[2]), "r"(a[3]), "r"(b[0]), "r"(b[1]));
}

// ---------------------------------------------------------------------------
// Pre-pass: round x and all W to tf32 once.
// ---------------------------------------------------------------------------
#define XN4 (M_ * D_ / 4)
#define WN4 (D_ * D_ / 4)
__global__ __launch_bounds__(256) void cvt_all(
    const float* __restrict__ x,
    const float* __restrict__ w0, const float* __restrict__ w1,
    const float* __restrict__ w2, const float* __restrict__ w3) {
    const int total = XN4 + 4 * WN4;
    for (int i = blockIdx.x * 256 + threadIdx.x; i < total;
         i += gridDim.x * 256) {
        const float4* src;
        float4* dst;
        if (i < XN4) { src = (const float4*)x + i; dst = (float4*)g_xr + i; }
        else {
            int r = i - XN4, wsel = r / WN4, off = r % WN4;
            const float* ws = wsel == 0 ? w0 : wsel == 1 ? w1 : wsel == 2 ? w2 : w3;
            src = (const float4*)ws + off;
            dst = (float4*)(g_wr + (size_t)wsel * D_ * D_) + off;
        }
        float4 v = *src;
        v.x = __uint_as_float(f2tf(v.x)); v.y = __uint_as_float(f2tf(v.y));
        v.z = __uint_as_float(f2tf(v.z)); v.w = __uint_as_float(f2tf(v.w));
        *dst = v;
    }
}

// ---------------------------------------------------------------------------
// tf32 mma.sync GEMM, 256 threads, tile 128x128, BK=32, cp.async double buffer.
// Warps 2(m) x 4(n): warp tile 64x32. smem stride 36 (conflict-free frags).
// Operands pre-rounded to tf32. ROUND: round output to tf32 (for q/k/v).
// ---------------------------------------------------------------------------
#define GEMM_SMEM (2 * 128 * 36 * 4 * 2)   // 73728 B

template <bool ROUND>
__device__ __forceinline__ void gemm_body(const float* __restrict__ A,
                                          const float* __restrict__ Bw,
                                          const float* __restrict__ bias,
                                          float* __restrict__ Cout) {
    extern __shared__ float smem_f[];
    float* As = smem_f;                  // [2][128][36]
    float* Bs = smem_f + 2 * 128 * 36;
    const uint32_t sA = smem_u32(As), sB = smem_u32(Bs);

    const int tid  = threadIdx.x;
    const int lane = tid & 31;
    const int warp = tid >> 5;
    const int g = lane >> 2, t = lane & 3;
    const int bm = blockIdx.y * 128;
    const int bn = blockIdx.x * 128;
    const int wm = (warp & 1) * 64;
    const int wn = (warp >> 1) * 32;

    float acc[4][4][4];
#pragma unroll
    for (int mi = 0; mi < 4; mi++)
#pragma unroll
        for (int nj = 0; nj < 4; nj++)
#pragma unroll
            for (int e = 0; e < 4; e++) acc[mi][nj][e] = 0.f;

    auto issue = [&](int j, int buf) {
#pragma unroll
        for (int p = 0; p < 4; p++) {
            int s_ = tid + p * 256; int r_ = s_ >> 3, c4_ = s_ & 7;
            uint32_t off = (uint32_t)((buf * 128 + r_) * 36 + c4_ * 4) * 4;
            cp_async16(sA + off, &A[(size_t)(bm + r_) * D_ + j * 32 + c4_ * 4]);
            cp_async16(sB + off, &Bw[(size_t)(bn + r_) * D_ + j * 32 + c4_ * 4]);
        }
    };

    issue(0, 0); CP_COMMIT();
    for (int j = 0; j < 32; j++) {
        const int buf = j & 1;
        if (j + 1 < 32) { issue(j + 1, buf ^ 1); CP_COMMIT(); CP_WAIT(1); }
        else            { CP_WAIT(0); }
        __syncthreads();

        const float* Ab = As + buf * 128 * 36;
        const float* Bb = Bs + buf * 128 * 36;
#pragma unroll
        for (int ks = 0; ks < 4; ks++) {
            const int cc = ks * 8 + t;
            uint32_t af[4][4];
#pragma unroll
            for (int mi = 0; mi < 4; mi++) {
                const int r0 = wm + mi * 16 + g;
                af[mi][0] = __float_as_uint(Ab[r0 * 36 + cc]);
                af[mi][1] = __float_as_uint(Ab[(r0 + 8) * 36 + cc]);
                af[mi][2] = __float_as_uint(Ab[r0 * 36 + cc + 4]);
                af[mi][3] = __float_as_uint(Ab[(r0 + 8) * 36 + cc + 4]);
            }
#pragma unroll
            for (int nj = 0; nj < 4; nj++) {
                uint32_t bf[2];
                const int rn = wn + nj * 8 + g;
                bf[0] = __float_as_uint(Bb[rn * 36 + cc]);
                bf[1] = __float_as_uint(Bb[rn * 36 + cc + 4]);
#pragma unroll
                for (int mi = 0; mi < 4; mi++) mma8(acc[mi][nj], af[mi], bf);
            }
        }
        __syncthreads();
    }

#pragma unroll
    for (int mi = 0; mi < 4; mi++) {
#pragma unroll
        for (int nj = 0; nj < 4; nj++) {
            const int col = bn + wn + nj * 8 + 2 * t;
            const float bx = bias[col], by = bias[col + 1];
            const int r0 = bm + wm + mi * 16 + g;
            float2 v0 = { acc[mi][nj][0] + bx, acc[mi][nj][1] + by };
            float2 v1 = { acc[mi][nj][2] + bx, acc[mi][nj][3] + by };
            if (ROUND) {
                v0.x = __uint_as_float(f2tf(v0.x)); v0.y = __uint_as_float(f2tf(v0.y));
                v1.x = __uint_as_float(f2tf(v1.x)); v1.y = __uint_as_float(f2tf(v1.y));
            }
            *(float2*)&Cout[(size_t)r0 * D_ + col] = v0;
            *(float2*)&Cout[(size_t)(r0 + 8) * D_ + col] = v1;
        }
    }
}

__global__ __launch_bounds__(256, 2) void gemm_qkv_tc(
    const float* __restrict__ bq, const float* __restrict__ bk,
    const float* __restrict__ bv) {
    const float* bias; float* C;
    const float* Wt = g_wr + (size_t)blockIdx.z * D_ * D_;
    if (blockIdx.z == 0)      { bias = bq; C = g_q; }
    else if (blockIdx.z == 1) { bias = bk; C = g_k; }
    else                      { bias = bv; C = g_v; }
    gemm_body<true>(g_xr, Wt, bias, C);
}

__global__ __launch_bounds__(256, 2) void gemm_out_tc(
    const float* __restrict__ bo, float* __restrict__ out) {
    gemm_body<false>(g_attn, g_wr + (size_t)3 * D_ * D_, bo, out);
}

// ---------------------------------------------------------------------------
// Sliding-window flash attention, 256 threads (8 warps x 16 q-rows).
// K/V pre-rounded tf32, cp.async double-buffered.
// Ks stride 68 (bank 4g+t injective), Vs stride 72 (bank 8t+g injective).
// ---------------------------------------------------------------------------
#define KS_STR 68
#define VS_STR 72
#define ATTN_SMEM (2 * 64 * KS_STR * 4 + 2 * 64 * VS_STR * 4)   // 71680 B

__global__ __launch_bounds__(256) void attn_tc() {
    extern __shared__ float smem_f[];
    float* Ks = smem_f;                     // [2][64][68]
    float* Vs = smem_f + 2 * 64 * KS_STR;   // [2][64][72]
    const uint32_t sK = smem_u32(Ks), sV = smem_u32(Vs);

    const int tid  = threadIdx.x;
    const int lane = tid & 31;
    const int warp = tid >> 5;
    const int g = lane >> 2, t = lane & 3;
    const int qt = blockIdx.x;            // 0..3
    const int h  = blockIdx.y;
    const int b  = blockIdx.z >> 3;
    const int c  = blockIdx.z & 7;
    const float qscale = 0.125f * 1.4426950408889634f;
    const int qrow0 = b * L_ + c * W_ + qt * 128 + warp * 16;

    // Q a-frags in registers for the whole kernel
    uint32_t qf[8][4];
#pragma unroll
    for (int ks = 0; ks < 8; ks++) {
        const int col = h * 64 + ks * 8 + t;
        const float* q0 = &g_q[(size_t)(qrow0 + g) * D_ + col];
        const float* q8 = &g_q[(size_t)(qrow0 + g + 8) * D_ + col];
        qf[ks][0] = f2tf(q0[0] * qscale);
        qf[ks][1] = f2tf(q8[0] * qscale);
        qf[ks][2] = f2tf(q0[4] * qscale);
        qf[ks][3] = f2tf(q8[4] * qscale);
    }

    float of[8][4];
    float mrow[2] = { -1e30f, -1e30f }, lrow[2] = { 0.f, 0.f };
#pragma unroll
    for (int nj = 0; nj < 8; nj++)
#pragma unroll
        for (int e = 0; e < 4; e++) of[nj][e] = 0.f;

    auto issueKV = [&](int kt, int buf) {
        const int tb = b * L_ + (c - 1) * W_ + kt * 64;
#pragma unroll
        for (int p = 0; p < 4; p++) {
            int s_ = tid + p * 256; int r_ = s_ >> 4, c4_ = s_ & 15;
            const size_t gb = (size_t)(tb + r_) * D_ + h * 64 + c4_ * 4;
            cp_async16(sK + (uint32_t)((buf * 64 + r_) * KS_STR + c4_ * 4) * 4, &g_k[gb]);
            cp_async16(sV + (uint32_t)((buf * 64 + r_) * VS_STR + c4_ * 4) * 4, &g_v[gb]);
        }
    };

    const int kt0 = (c == 0) ? 8 : 0;   // chunk 0 lookback is padding -> skip
    issueKV(kt0, 0); CP_COMMIT();
    for (int kt = kt0; kt < 16; kt++) {
        const int buf = (kt - kt0) & 1;
        if (kt + 1 < 16) { issueKV(kt + 1, buf ^ 1); CP_COMMIT(); CP_WAIT(1); }
        else             { CP_WAIT(0); }
        __syncthreads();

        const float* Kb = Ks + buf * 64 * KS_STR;
        const float* Vb = Vs + buf * 64 * VS_STR;

        // S = Q @ K^T
        float s[8][4];
#pragma unroll
        for (int nj = 0; nj < 8; nj++)
#pragma unroll
            for (int e = 0; e < 4; e++) s[nj][e] = 0.f;
#pragma unroll
        for (int ks = 0; ks < 8; ks++) {
            const int cc = ks * 8 + t;
#pragma unroll
            for (int nj = 0; nj < 8; nj++) {
                uint32_t bf[2];
                bf[0] = __float_as_uint(Kb[(nj * 8 + g) * KS_STR + cc]);
                bf[1] = __float_as_uint(Kb[(nj * 8 + g) * KS_STR + cc + 4]);
                mma8(s[nj], qf[ks], bf);
            }
        }

        // Online softmax (base-2 domain; row = quad of 4 lanes)
#pragma unroll
        for (int hh = 0; hh < 2; hh++) {
            const int e0 = hh * 2;
            float mx = -1e30f;
#pragma unroll
            for (int nj = 0; nj < 8; nj++)
                mx = fmaxf(mx, fmaxf(s[nj][e0], s[nj][e0 + 1]));
            mx = fmaxf(mx, __shfl_xor_sync(0xffffffffu, mx, 1));
            mx = fmaxf(mx, __shfl_xor_sync(0xffffffffu, mx, 2));
            const float mnew = fmaxf(mrow[hh], mx);
            const float corr = ex2(mrow[hh] - mnew);
            float rs = 0.f;
#pragma unroll
            for (int nj = 0; nj < 8; nj++) {
                float p0 = ex2(s[nj][e0] - mnew);
                float p1 = ex2(s[nj][e0 + 1] - mnew);
                s[nj][e0] = p0; s[nj][e0 + 1] = p1;
                rs += p0 + p1;
                of[nj][e0] *= corr;
                of[nj][e0 + 1] *= corr;
            }
            rs += __shfl_xor_sync(0xffffffffu, rs, 1);
            rs += __shfl_xor_sync(0xffffffffu, rs, 2);
            lrow[hh] = lrow[hh] * corr + rs;
            mrow[hh] = mnew;
        }

        // O += P @ V. P C-frag -> A-frag via quad shuffles.
        const int qb = lane & 28;
        const int srcA = qb | (t >> 1);
        const int srcB = qb | ((t >> 1) + 2);
        const bool odd = (t & 1);
#pragma unroll
        for (int kk = 0; kk < 8; kk++) {
            float x0 = __shfl_sync(0xffffffffu, s[kk][0], srcA);
            float x1 = __shfl_sync(0xffffffffu, s[kk][1], srcA);
            float x2 = __shfl_sync(0xffffffffu, s[kk][2], srcA);
            float x3 = __shfl_sync(0xffffffffu, s[kk][3], srcA);
            float y0 = __shfl_sync(0xffffffffu, s[kk][0], srcB);
            float y1 = __shfl_sync(0xffffffffu, s[kk][1], srcB);
            float y2 = __shfl_sync(0xffffffffu, s[kk][2], srcB);
            float y3 = __shfl_sync(0xffffffffu, s[kk][3], srcB);
            uint32_t am[4];
            am[0] = f2tf(odd ? x1 : x0);
            am[1] = f2tf(odd ? x3 : x2);
            am[2] = f2tf(odd ? y1 : y0);
            am[3] = f2tf(odd ? y3 : y2);
#pragma unroll
            for (int nj = 0; nj < 8; nj++) {
                uint32_t bf[2];
                bf[0] = __float_as_uint(Vb[(kk * 8 + t) * VS_STR + nj * 8 + g]);
                bf[1] = __float_as_uint(Vb[(kk * 8 + t + 4) * VS_STR + nj * 8 + g]);
                mma8(of[nj], am, bf);
            }
        }
        __syncthreads();
    }

    // Epilogue: normalize, round to tf32 (feeds out-proj A operand), write
    const float inv0 = 1.f / lrow[0];
    const float inv1 = 1.f / lrow[1];
#pragma unroll
    for (int nj = 0; nj < 8; nj++) {
        const int col = h * 64 + nj * 8 + 2 * t;
        float2 v0 = { __uint_as_float(f2tf(of[nj][0] * inv0)),
                      __uint_as_float(f2tf(of[nj][1] * inv0)) };
        float2 v1 = { __uint_as_float(f2tf(of[nj][2] * inv1)),
                      __uint_as_float(f2tf(of[nj][3] * inv1)) };
        *(float2*)&g_attn[(size_t)(qrow0 + g) * D_ + col] = v0;
        *(float2*)&g_attn[(size_t)(qrow0 + g + 8) * D_ + col] = v1;
    }
}

// ---------------------------------------------------------------------------
extern "C" void kernel_launch(void* const* d_in, const int* in_sizes, int n_in,
                              void* d_out, int out_size) {
    const float* x  = (const float*)d_in[0];
    const float* Wq = (const float*)d_in[1];
    const float* bq = (const float*)d_in[2];
    const float* Wk = (const float*)d_in[3];
    const float* bk = (const float*)d_in[4];
    const float* Wv = (const float*)d_in[5];
    const float* bv = (const float*)d_in[6];
    const float* Wo = (const float*)d_in[7];
    const float* bo = (const float*)d_in[8];
    float* out = (float*)d_out;

    static int configured = 0;
    if (!configured) {
        cudaFuncSetAttribute(gemm_qkv_tc, cudaFuncAttributeMaxDynamicSharedMemorySize, GEMM_SMEM);
        cudaFuncSetAttribute(gemm_out_tc, cudaFuncAttributeMaxDynamicSharedMemorySize, GEMM_SMEM);
        cudaFuncSetAttribute(attn_tc, cudaFuncAttributeMaxDynamicSharedMemorySize, ATTN_SMEM);
        configured = 1;
    }

    cvt_all<<<1024, 256>>>(x, Wq, Wk, Wv, Wo);
    gemm_qkv_tc<<<dim3(D_ / 128, M_ / 128, 3), 256, GEMM_SMEM>>>(bq, bk, bv);
    attn_tc<<<dim3(4, H_, B_ * C_), 256, ATTN_SMEM>>>();
    gemm_out_tc<<<dim3(D_ / 128, M_ / 128), 256, GEMM_SMEM>>>(bo, out);
}

// round 12
// speedup vs baseline: 7.3560x; 1.7709x over previous
#include <cuda_runtime.h>
#include <cuda_fp16.h>
#include <cstdint>

#define B_  2
#define L_  4096
#define D_  1024
#define H_  16
#define W_  512
#define C_  8
#define M_  (B_ * L_)

// Scratch (device globals: allocation-free per harness rules)
__device__ __half g_xh[M_ * D_];        // x rounded to f16
__device__ __half g_wh[4 * D_ * D_];    // Wq,Wk,Wv,Wo rounded to f16
__device__ __half g_qh[M_ * D_];        // q * 0.125*log2e, f16
__device__ __half g_kh[M_ * D_];        // k, f16
__device__ __half g_vt[M_ * D_];        // v transposed: [b][h][d][token]
__device__ __half g_ah[M_ * D_];        // attention out, f16

// ---------------------------------------------------------------------------
// helpers
// ---------------------------------------------------------------------------
__device__ __forceinline__ float ex2(float x) {
    float y;
    asm("ex2.approx.ftz.f32 %0, %1;" : "=f"(y) : "f"(x));
    return y;
}
__device__ __forceinline__ uint32_t smem_u32(const void* p) {
    uint32_t a;
    asm("{ .reg .u64 t; cvta.to.shared.u64 t, %1; cvt.u32.u64 %0, t; }"
        : "=r"(a) : "l"(p));
    return a;
}
__device__ __forceinline__ void cp_async16(uint32_t dst, const void* src) {
    asm volatile("cp.async.cg.shared.global [%0], [%1], 16;" :: "r"(dst), "l"(src));
}
#define CP_COMMIT()  asm volatile("cp.async.commit_group;" ::: "memory")
#define CP_WAIT(n)   asm volatile("cp.async.wait_group %0;" :: "n"(n) : "memory")

__device__ __forceinline__ uint32_t h2pack(float lo, float hi) {
    __half2 h = __floats2half2_rn(lo, hi);
    return *(uint32_t*)&h;
}

// D += A*B, m16n8k16 f16, f32 accum
__device__ __forceinline__ void mma16(float* d, const uint32_t* a, const uint32_t* b) {
    asm volatile(
        "mma.sync.aligned.m16n8k16.row.col.f32.f16.f16.f32 "
        "{%0,%1,%2,%3}, {%4,%5,%6,%7}, {%8,%9}, {%0,%1,%2,%3};"
        : "+f"(d[0]), "+f"(d[1]), "+f"(d[2]), "+f"(d[3])
        : "r"(a[0]), "r"(a[1]), "r"(a[2]), "r"(a[3]), "r"(b[0]), "r"(b[1]));
}

// ---------------------------------------------------------------------------
// Pre-pass: x and 4x W -> f16 once.
// ---------------------------------------------------------------------------
__global__ __launch_bounds__(256) void cvt_all(
    const float* __restrict__ x,
    const float* __restrict__ w0, const float* __restrict__ w1,
    const float* __restrict__ w2, const float* __restrict__ w3) {
    const int XN8 = M_ * D_ / 8;
    const int WN8 = D_ * D_ / 8;
    const int total = XN8 + 4 * WN8;
    for (int i = blockIdx.x * 256 + threadIdx.x; i < total; i += gridDim.x * 256) {
        const float4* src;
        __half* dst;
        if (i < XN8) { src = (const float4*)x + 2 * i; dst = g_xh + 8 * i; }
        else {
            int r = i - XN8, wsel = r / WN8, off = r % WN8;
            const float* ws = wsel == 0 ? w0 : wsel == 1 ? w1 : wsel == 2 ? w2 : w3;
            src = (const float4*)ws + 2 * off;
            dst = g_wh + (size_t)wsel * D_ * D_ + 8 * off;
        }
        float4 v0 = src[0], v1 = src[1];
        uint32_t o[4];
        o[0] = h2pack(v0.x, v0.y); o[1] = h2pack(v0.z, v0.w);
        o[2] = h2pack(v1.x, v1.y); o[3] = h2pack(v1.z, v1.w);
        *(uint4*)dst = *(uint4*)o;
    }
}

// ---------------------------------------------------------------------------
// f16 mma.sync GEMM: C[m][n] = sum_k A[m][k]*Bw[n][k] + bias[n]
// 256 threads, tile 128x128, BK=32 f16, 4-stage cp.async, 1 sync/iter.
// smem rows padded to 20 b32 (bank 4g+t injective).
// mode: 0 = fp32 out, 1 = f16 out (k), 2 = f16 out scaled (q), 3 = f16
// transposed out (v -> g_vt).
// ---------------------------------------------------------------------------
#define KSTR 20                     // b32 per smem row
#define GEMM_SMEM (4 * 2 * 128 * KSTR * 4)   // 81920 B
#define QSCALE (0.125f * 1.4426950408889634f)

__device__ __forceinline__ void gemm_f16_body(
    const __half* __restrict__ A, const __half* __restrict__ Bw,
    const float* __restrict__ bias, void* __restrict__ outp, int mode) {
    extern __shared__ float smem_f[];
    uint32_t* As = (uint32_t*)smem_f;             // [4][128][20]
    uint32_t* Bs = As + 4 * 128 * KSTR;
    const uint32_t sA = smem_u32(As), sB = smem_u32(Bs);

    const int tid  = threadIdx.x;
    const int lane = tid & 31;
    const int warp = tid >> 5;
    const int g = lane >> 2, t = lane & 3;
    const int bm = blockIdx.y * 128;
    const int bn = blockIdx.x * 128;
    const int wm = (warp & 1) * 64;
    const int wn = (warp >> 1) * 32;

    float acc[4][4][4];
#pragma unroll
    for (int mi = 0; mi < 4; mi++)
#pragma unroll
        for (int nj = 0; nj < 4; nj++)
#pragma unroll
            for (int e = 0; e < 4; e++) acc[mi][nj][e] = 0.f;

#define ISSUE(j, stg)                                                          \
    {                                                                          \
        _Pragma("unroll")                                                      \
        for (int p = 0; p < 2; p++) {                                          \
            int s_ = tid + p * 256;                                            \
            int r_ = s_ >> 2, c4_ = s_ & 3;                                    \
            uint32_t off = (uint32_t)(((stg) * 128 + r_) * KSTR + c4_ * 4) * 4;\
            cp_async16(sA + off, &A[(size_t)(bm + r_) * D_ + (j) * 32 + c4_ * 8]); \
            cp_async16(sB + off, &Bw[(size_t)(bn + r_) * D_ + (j) * 32 + c4_ * 8]); \
        }                                                                      \
    }

    ISSUE(0, 0); CP_COMMIT();
    ISSUE(1, 1); CP_COMMIT();
    ISSUE(2, 2); CP_COMMIT();

    const int NIT = D_ / 32;   // 32 iters
    for (int j = 0; j < NIT; j++) {
        const int stg = j & 3;
        CP_WAIT(2);
        __syncthreads();
        if (j + 3 < NIT) { ISSUE(j + 3, (j + 3) & 3); }
        CP_COMMIT();

        const uint32_t* Ab = As + stg * 128 * KSTR;
        const uint32_t* Bb = Bs + stg * 128 * KSTR;
#pragma unroll
        for (int ks = 0; ks < 2; ks++) {
            const int cc = ks * 8 + t;
            uint32_t af[4][4];
#pragma unroll
            for (int mi = 0; mi < 4; mi++) {
                const int r0 = wm + mi * 16 + g;
                af[mi][0] = Ab[r0 * KSTR + cc];
                af[mi][1] = Ab[(r0 + 8) * KSTR + cc];
                af[mi][2] = Ab[r0 * KSTR + cc + 4];
                af[mi][3] = Ab[(r0 + 8) * KSTR + cc + 4];
            }
#pragma unroll
            for (int nj = 0; nj < 4; nj++) {
                uint32_t bf[2];
                const int rn = wn + nj * 8 + g;
                bf[0] = Bb[rn * KSTR + cc];
                bf[1] = Bb[rn * KSTR + cc + 4];
#pragma unroll
                for (int mi = 0; mi < 4; mi++) mma16(acc[mi][nj], af[mi], bf);
            }
        }
    }

    if (mode == 0) {
        float* Cout = (float*)outp;
#pragma unroll
        for (int mi = 0; mi < 4; mi++)
#pragma unroll
            for (int nj = 0; nj < 4; nj++) {
                const int col = bn + wn + nj * 8 + 2 * t;
                const float bx = bias[col], by = bias[col + 1];
                const int r0 = bm + wm + mi * 16 + g;
                float2 v0 = { acc[mi][nj][0] + bx, acc[mi][nj][1] + by };
                float2 v1 = { acc[mi][nj][2] + bx, acc[mi][nj][3] + by };
                *(float2*)&Cout[(size_t)r0 * D_ + col] = v0;
                *(float2*)&Cout[(size_t)(r0 + 8) * D_ + col] = v1;
            }
    } else if (mode == 3) {
        // V: transpose through smem, then coalesced f16 stores to g_vt.
        __syncthreads();
        __half* Tt = (__half*)smem_f;   // [128 d-cols][136 tokens-padded]
#pragma unroll
        for (int mi = 0; mi < 4; mi++)
#pragma unroll
            for (int nj = 0; nj < 4; nj++) {
                const int cl = wn + nj * 8 + 2 * t;
                const float bx = bias[bn + cl], by = bias[bn + cl + 1];
                const int r0 = wm + mi * 16 + g;
                Tt[cl * 136 + r0]       = __float2half_rn(acc[mi][nj][0] + bx);
                Tt[(cl + 1) * 136 + r0] = __float2half_rn(acc[mi][nj][1] + by);
                Tt[cl * 136 + r0 + 8]       = __float2half_rn(acc[mi][nj][2] + bx);
                Tt[(cl + 1) * 136 + r0 + 8] = __float2half_rn(acc[mi][nj][3] + by);
            }
        __syncthreads();
        const int bb = bm >> 12;           // batch
        const int tok0 = bm & (L_ - 1);
        // 128 d-cols x 128 tokens = 2048 float4 units (16 per d-col)
#pragma unroll
        for (int p = 0; p < 8; p++) {
            int i = tid + p * 256;
            int row = i >> 4, f4 = i & 15;   // row: local d-col, f4: 8-token unit
            const int gc = bn + row;
            const int hh = gc >> 6, dl = gc & 63;
            float4 v = *(float4*)&Tt[row * 136 + f4 * 8];
            *(float4*)&g_vt[((size_t)((bb * H_ + hh) * 64 + dl)) * L_ + tok0 + f4 * 8] = v;
        }
    } else {
        const float sc = (mode == 2) ? QSCALE : 1.f;
        __half* Cout = (mode == 2) ? g_qh : g_kh;
#pragma unroll
        for (int mi = 0; mi < 4; mi++)
#pragma unroll
            for (int nj = 0; nj < 4; nj++) {
                const int col = bn + wn + nj * 8 + 2 * t;
                const float bx = bias[col], by = bias[col + 1];
                const int r0 = bm + wm + mi * 16 + g;
                uint32_t v0 = h2pack((acc[mi][nj][0] + bx) * sc, (acc[mi][nj][1] + by) * sc);
                uint32_t v1 = h2pack((acc[mi][nj][2] + bx) * sc, (acc[mi][nj][3] + by) * sc);
                *(uint32_t*)&Cout[(size_t)r0 * D_ + col] = v0;
                *(uint32_t*)&Cout[(size_t)(r0 + 8) * D_ + col] = v1;
            }
    }
#undef ISSUE
}

__global__ __launch_bounds__(256, 2) void gemm_qkv_f16(
    const float* __restrict__ bq, const float* __restrict__ bk,
    const float* __restrict__ bv) {
    const __half* Wt = g_wh + (size_t)blockIdx.z * D_ * D_;
    const float* bias;
    int mode;
    if (blockIdx.z == 0)      { bias = bq; mode = 2; }
    else if (blockIdx.z == 1) { bias = bk; mode = 1; }
    else                      { bias = bv; mode = 3; }
    gemm_f16_body(g_xh, Wt, bias, nullptr, mode);
}

__global__ __launch_bounds__(256, 2) void gemm_out_f16(
    const float* __restrict__ bo, float* __restrict__ out) {
    gemm_f16_body(g_ah, g_wh + (size_t)3 * D_ * D_, bo, out, 0);
}

// ---------------------------------------------------------------------------
// Sliding-window flash attention, f16 mma, 256 threads (8 warps x 16 q-rows).
// Ks [key][d] stride 36 b32; Vt [d][token] stride 36 b32 (both bank-injective).
// P: C-frag == A-frag in f16 -> zero shuffles.
// ---------------------------------------------------------------------------
#define AKSTR 36
#define ATTN_SMEM (2 * 2 * 64 * AKSTR * 4)   // 36864 B

__global__ __launch_bounds__(256) void attn_f16() {
    extern __shared__ float smem_f[];
    uint32_t* Ks = (uint32_t*)smem_f;           // [2][64][36]
    uint32_t* Vs = Ks + 2 * 64 * AKSTR;         // [2][64][36]
    const uint32_t sK = smem_u32(Ks), sV = smem_u32(Vs);

    const int tid  = threadIdx.x;
    const int lane = tid & 31;
    const int warp = tid >> 5;
    const int g = lane >> 2, t = lane & 3;
    const int qt = blockIdx.x;            // 0..3
    const int h  = blockIdx.y;
    const int b  = blockIdx.z >> 3;
    const int c  = blockIdx.z & 7;
    const int qrow0 = b * L_ + c * W_ + qt * 128 + warp * 16;

    // Q a-frags (scale pre-folded into g_qh). b32 view: 512 per row.
    const uint32_t* q32 = (const uint32_t*)g_qh;
    uint32_t qf[4][4];
#pragma unroll
    for (int ks = 0; ks < 4; ks++) {
        const int cc = h * 32 + ks * 8 + t;
        qf[ks][0] = q32[(size_t)(qrow0 + g) * 512 + cc];
        qf[ks][1] = q32[(size_t)(qrow0 + g + 8) * 512 + cc];
        qf[ks][2] = q32[(size_t)(qrow0 + g) * 512 + cc + 4];
        qf[ks][3] = q32[(size_t)(qrow0 + g + 8) * 512 + cc + 4];
    }

    float of[8][4];
    float mrow[2] = { -1e30f, -1e30f }, lrow[2] = { 0.f, 0.f };
#pragma unroll
    for (int nj = 0; nj < 8; nj++)
#pragma unroll
        for (int e = 0; e < 4; e++) of[nj][e] = 0.f;

    const __half* kh = g_kh;
    const size_t vtbase = (size_t)(b * H_ + h) * 64 * L_;

    auto issueKV = [&](int kt, int buf) {
        const int tok = (c - 1) * W_ + kt * 64;
#pragma unroll
        for (int p = 0; p < 2; p++) {
            int s_ = tid + p * 256;
            int r_ = s_ >> 3, c4_ = s_ & 7;   // 8 x 16B per 64-wide f16 row
            uint32_t off = (uint32_t)((buf * 64 + r_) * AKSTR + c4_ * 4) * 4;
            cp_async16(sK + off, &kh[(size_t)(b * L_ + tok + r_) * D_ + h * 64 + c4_ * 8]);
            cp_async16(sV + off, &g_vt[vtbase + (size_t)r_ * L_ + tok + c4_ * 8]);
        }
    };

    const int kt0 = (c == 0) ? 8 : 0;   // chunk 0 lookback is padding
    issueKV(kt0, 0); CP_COMMIT();
    for (int kt = kt0; kt < 16; kt++) {
        const int buf = (kt - kt0) & 1;
        if (kt + 1 < 16) { issueKV(kt + 1, buf ^ 1); CP_COMMIT(); CP_WAIT(1); }
        else             { CP_WAIT(0); }
        __syncthreads();

        const uint32_t* Kb = Ks + buf * 64 * AKSTR;
        const uint32_t* Vb = Vs + buf * 64 * AKSTR;

        // S = Q @ K^T
        float s[8][4];
#pragma unroll
        for (int nj = 0; nj < 8; nj++)
#pragma unroll
            for (int e = 0; e < 4; e++) s[nj][e] = 0.f;
#pragma unroll
        for (int ks = 0; ks < 4; ks++) {
            const int cc = ks * 8 + t;
#pragma unroll
            for (int nj = 0; nj < 8; nj++) {
                uint32_t bf[2];
                bf[0] = Kb[(nj * 8 + g) * AKSTR + cc];
                bf[1] = Kb[(nj * 8 + g) * AKSTR + cc + 4];
                mma16(s[nj], qf[ks], bf);
            }
        }

        // Online softmax (base-2; row = quad of 4 lanes)
#pragma unroll
        for (int hh = 0; hh < 2; hh++) {
            const int e0 = hh * 2;
            float mx = -1e30f;
#pragma unroll
            for (int nj = 0; nj < 8; nj++)
                mx = fmaxf(mx, fmaxf(s[nj][e0], s[nj][e0 + 1]));
            mx = fmaxf(mx, __shfl_xor_sync(0xffffffffu, mx, 1));
            mx = fmaxf(mx, __shfl_xor_sync(0xffffffffu, mx, 2));
            const float mnew = fmaxf(mrow[hh], mx);
            const float corr = ex2(mrow[hh] - mnew);
            float rs = 0.f;
#pragma unroll
            for (int nj = 0; nj < 8; nj++) {
                float p0 = ex2(s[nj][e0] - mnew);
                float p1 = ex2(s[nj][e0 + 1] - mnew);
                s[nj][e0] = p0; s[nj][e0 + 1] = p1;
                rs += p0 + p1;
                of[nj][e0] *= corr;
                of[nj][e0 + 1] *= corr;
            }
            rs += __shfl_xor_sync(0xffffffffu, rs, 1);
            rs += __shfl_xor_sync(0xffffffffu, rs, 2);
            lrow[hh] = lrow[hh] * corr + rs;
            mrow[hh] = mnew;
        }

        // O += P @ V: pack adjacent S tiles into f16 A-frags (no shuffles!)
#pragma unroll
        for (int kk = 0; kk < 4; kk++) {
            uint32_t am[4];
            am[0] = h2pack(s[2 * kk][0], s[2 * kk][1]);
            am[1] = h2pack(s[2 * kk][2], s[2 * kk][3]);
            am[2] = h2pack(s[2 * kk + 1][0], s[2 * kk + 1][1]);
            am[3] = h2pack(s[2 * kk + 1][2], s[2 * kk + 1][3]);
#pragma unroll
            for (int nj = 0; nj < 8; nj++) {
                uint32_t bf[2];
                bf[0] = Vb[(nj * 8 + g) * AKSTR + kk * 8 + t];
                bf[1] = Vb[(nj * 8 + g) * AKSTR + kk * 8 + t + 4];
                mma16(of[nj], am, bf);
            }
        }
        __syncthreads();
    }

    // Epilogue: normalize, f16 store to g_ah
    const float inv0 = 1.f / lrow[0];
    const float inv1 = 1.f / lrow[1];
#pragma unroll
    for (int nj = 0; nj < 8; nj++) {
        const int col = h * 64 + nj * 8 + 2 * t;
        uint32_t v0 = h2pack(of[nj][0] * inv0, of[nj][1] * inv0);
        uint32_t v1 = h2pack(of[nj][2] * inv1, of[nj][3] * inv1);
        *(uint32_t*)&g_ah[(size_t)(qrow0 + g) * D_ + col] = v0;
        *(uint32_t*)&g_ah[(size_t)(qrow0 + g + 8) * D_ + col] = v1;
    }
}

// ---------------------------------------------------------------------------
extern "C" void kernel_launch(void* const* d_in, const int* in_sizes, int n_in,
                              void* d_out, int out_size) {
    const float* x  = (const float*)d_in[0];
    const float* Wq = (const float*)d_in[1];
    const float* bq = (const float*)d_in[2];
    const float* Wk = (const float*)d_in[3];
    const float* bk = (const float*)d_in[4];
    const float* Wv = (const float*)d_in[5];
    const float* bv = (const float*)d_in[6];
    const float* Wo = (const float*)d_in[7];
    const float* bo = (const float*)d_in[8];
    float* out = (float*)d_out;

    cudaFuncSetAttribute(gemm_qkv_f16, cudaFuncAttributeMaxDynamicSharedMemorySize, GEMM_SMEM);
    cudaFuncSetAttribute(gemm_out_f16, cudaFuncAttributeMaxDynamicSharedMemorySize, GEMM_SMEM);
    cudaFuncSetAttribute(attn_f16, cudaFuncAttributeMaxDynamicSharedMemorySize, ATTN_SMEM);

    cvt_all<<<1024, 256>>>(x, Wq, Wk, Wv, Wo);
    gemm_qkv_f16<<<dim3(D_ / 128, M_ / 128, 3), 256, GEMM_SMEM>>>(bq, bk, bv);
    attn_f16<<<dim3(4, H_, B_ * C_), 256, ATTN_SMEM>>>();
    gemm_out_f16<<<dim3(D_ / 128, M_ / 128), 256, GEMM_SMEM>>>(bo, out);
}

// round 14
// speedup vs baseline: 7.9337x; 1.0785x over previous
#include <cuda_runtime.h>
#include <cuda_fp16.h>
#include <cstdint>

#define B_  2
#define L_  4096
#define D_  1024
#define H_  16
#define W_  512
#define C_  8
#define M_  (B_ * L_)

// Scratch (device globals: allocation-free per harness rules)
__device__ __half g_xh[M_ * D_];        // x rounded to f16
__device__ __half g_wh[4 * D_ * D_];    // Wq,Wk,Wv,Wo rounded to f16
__device__ __half g_qh[M_ * D_];        // q * 0.125*log2e, f16
__device__ __half g_kh[M_ * D_];        // k, f16
__device__ __half g_vt[M_ * D_];        // v transposed: [b][h][d][token]
__device__ __half g_ah[M_ * D_];        // attention out, f16

// ---------------------------------------------------------------------------
// helpers
// ---------------------------------------------------------------------------
__device__ __forceinline__ float ex2(float x) {
    float y;
    asm("ex2.approx.ftz.f32 %0, %1;" : "=f"(y) : "f"(x));
    return y;
}
__device__ __forceinline__ uint32_t smem_u32(const void* p) {
    uint32_t a;
    asm("{ .reg .u64 t; cvta.to.shared.u64 t, %1; cvt.u32.u64 %0, t; }"
        : "=r"(a) : "l"(p));
    return a;
}
__device__ __forceinline__ void cp_async16(uint32_t dst, const void* src) {
    asm volatile("cp.async.cg.shared.global [%0], [%1], 16;" :: "r"(dst), "l"(src));
}
#define CP_COMMIT()  asm volatile("cp.async.commit_group;" ::: "memory")
#define CP_WAIT(n)   asm volatile("cp.async.wait_group %0;" :: "n"(n) : "memory")

__device__ __forceinline__ uint32_t h2pack(float lo, float hi) {
    __half2 h = __floats2half2_rn(lo, hi);
    return *(uint32_t*)&h;
}

// ldmatrix x4: 4 8x8 b16 matrices, lane i supplies row address
__device__ __forceinline__ void ldsm4(uint32_t* r, uint32_t a) {
    asm volatile("ldmatrix.sync.aligned.m8n8.x4.shared.b16 {%0,%1,%2,%3}, [%4];"
        : "=r"(r[0]), "=r"(r[1]), "=r"(r[2]), "=r"(r[3]) : "r"(a));
}

// D += A*B, m16n8k16 f16, f32 accum
__device__ __forceinline__ void mma16(float* d, const uint32_t* a, const uint32_t* b) {
    asm volatile(
        "mma.sync.aligned.m16n8k16.row.col.f32.f16.f16.f32 "
        "{%0,%1,%2,%3}, {%4,%5,%6,%7}, {%8,%9}, {%0,%1,%2,%3};"
        : "+f"(d[0]), "+f"(d[1]), "+f"(d[2]), "+f"(d[3])
        : "r"(a[0]), "r"(a[1]), "r"(a[2]), "r"(a[3]), "r"(b[0]), "r"(b[1]));
}

// ---------------------------------------------------------------------------
// Pre-pass: x and 4x W -> f16 once.
// ---------------------------------------------------------------------------
__global__ __launch_bounds__(256) void cvt_all(
    const float* __restrict__ x,
    const float* __restrict__ w0, const float* __restrict__ w1,
    const float* __restrict__ w2, const float* __restrict__ w3) {
    const int XN8 = M_ * D_ / 8;
    const int WN8 = D_ * D_ / 8;
    const int total = XN8 + 4 * WN8;
    for (int i = blockIdx.x * 256 + threadIdx.x; i < total; i += gridDim.x * 256) {
        const float4* src;
        __half* dst;
        if (i < XN8) { src = (const float4*)x + 2 * i; dst = g_xh + 8 * i; }
        else {
            int r = i - XN8, wsel = r / WN8, off = r % WN8;
            const float* ws = wsel == 0 ? w0 : wsel == 1 ? w1 : wsel == 2 ? w2 : w3;
            src = (const float4*)ws + 2 * off;
            dst = g_wh + (size_t)wsel * D_ * D_ + 8 * off;
        }
        float4 v0 = src[0], v1 = src[1];
        uint32_t o[4];
        o[0] = h2pack(v0.x, v0.y); o[1] = h2pack(v0.z, v0.w);
        o[2] = h2pack(v1.x, v1.y); o[3] = h2pack(v1.z, v1.w);
        *(uint4*)dst = *(uint4*)o;
    }
}

// ---------------------------------------------------------------------------
// f16 mma.sync GEMM with ldmatrix operand fetch.
// 256 threads, tile 128x128, BK=32 f16, 4-stage cp.async, 1 sync/iter.
// smem rows padded to 20 b32 (LDSM: 8 rows stride-20 cover all 32 banks).
// mode: 0 fp32 out, 1 f16 (k), 2 f16 scaled (q), 3 f16 transposed (v->g_vt).
// ---------------------------------------------------------------------------
#define KSTR 20                     // b32 per smem row
#define GEMM_SMEM (4 * 2 * 128 * KSTR * 4)   // 81920 B
#define QSCALE (0.125f * 1.4426950408889634f)

__device__ __forceinline__ void gemm_f16_body(
    const __half* __restrict__ A, const __half* __restrict__ Bw,
    const float* __restrict__ bias, void* __restrict__ outp, int mode) {
    extern __shared__ float smem_f[];
    uint32_t* As = (uint32_t*)smem_f;             // [4][128][20]
    uint32_t* Bs = As + 4 * 128 * KSTR;
    const uint32_t sA = smem_u32(As), sB = smem_u32(Bs);

    const int tid  = threadIdx.x;
    const int lane = tid & 31;
    const int warp = tid >> 5;
    const int g = lane >> 2, t = lane & 3;
    const int bm = blockIdx.y * 128;
    const int bn = blockIdx.x * 128;
    const int wm = (warp & 1) * 64;
    const int wn = (warp >> 1) * 32;

    // LDSM per-lane base offsets (b32 units within one stage buffer)
    const int l8 = lane & 7;
    const uint32_t aOff = (uint32_t)((wm + l8 + ((lane >> 3) & 1) * 8) * KSTR
                                     + (lane >> 4) * 4);
    const uint32_t bOff = (uint32_t)((wn + l8 + (lane >> 4) * 8) * KSTR
                                     + ((lane >> 3) & 1) * 4);

    float acc[4][4][4];
#pragma unroll
    for (int mi = 0; mi < 4; mi++)
#pragma unroll
        for (int nj = 0; nj < 4; nj++)
#pragma unroll
            for (int e = 0; e < 4; e++) acc[mi][nj][e] = 0.f;

#define ISSUE(j, stg)                                                          \
    {                                                                          \
        _Pragma("unroll")                                                      \
        for (int p = 0; p < 2; p++) {                                          \
            int s_ = tid + p * 256;                                            \
            int r_ = s_ >> 2, c4_ = s_ & 3;                                    \
            uint32_t off = (uint32_t)(((stg) * 128 + r_) * KSTR + c4_ * 4) * 4;\
            cp_async16(sA + off, &A[(size_t)(bm + r_) * D_ + (j) * 32 + c4_ * 8]); \
            cp_async16(sB + off, &Bw[(size_t)(bn + r_) * D_ + (j) * 32 + c4_ * 8]); \
        }                                                                      \
    }

    ISSUE(0, 0); CP_COMMIT();
    ISSUE(1, 1); CP_COMMIT();
    ISSUE(2, 2); CP_COMMIT();

    const int NIT = D_ / 32;   // 32 iters
    for (int j = 0; j < NIT; j++) {
        const int stg = j & 3;
        CP_WAIT(2);
        __syncthreads();
        if (j + 3 < NIT) { ISSUE(j + 3, (j + 3) & 3); }
        CP_COMMIT();

        const uint32_t baseA = sA + (uint32_t)(stg * 128 * KSTR) * 4;
        const uint32_t baseB = sB + (uint32_t)(stg * 128 * KSTR) * 4;
#pragma unroll
        for (int ks = 0; ks < 2; ks++) {
            uint32_t af[4][4];
#pragma unroll
            for (int mi = 0; mi < 4; mi++)
                ldsm4(af[mi], baseA + (aOff + mi * 16 * KSTR + ks * 8) * 4);
            uint32_t bfp[2][4];
#pragma unroll
            for (int np = 0; np < 2; np++)
                ldsm4(bfp[np], baseB + (bOff + np * 16 * KSTR + ks * 8) * 4);
#pragma unroll
            for (int nj = 0; nj < 4; nj++) {
                const uint32_t* bf = &bfp[nj >> 1][(nj & 1) * 2];
#pragma unroll
                for (int mi = 0; mi < 4; mi++) mma16(acc[mi][nj], af[mi], bf);
            }
        }
    }

    if (mode == 0) {
        float* Cout = (float*)outp;
#pragma unroll
        for (int mi = 0; mi < 4; mi++)
#pragma unroll
            for (int nj = 0; nj < 4; nj++) {
                const int col = bn + wn + nj * 8 + 2 * t;
                const float bx = bias[col], by = bias[col + 1];
                const int r0 = bm + wm + mi * 16 + g;
                float2 v0 = { acc[mi][nj][0] + bx, acc[mi][nj][1] + by };
                float2 v1 = { acc[mi][nj][2] + bx, acc[mi][nj][3] + by };
                *(float2*)&Cout[(size_t)r0 * D_ + col] = v0;
                *(float2*)&Cout[(size_t)(r0 + 8) * D_ + col] = v1;
            }
    } else if (mode == 3) {
        // V: transpose through smem, then coalesced f16 stores to g_vt.
        __syncthreads();
        __half* Tt = (__half*)smem_f;   // [128 d-cols][136 tokens-padded]
#pragma unroll
        for (int mi = 0; mi < 4; mi++)
#pragma unroll
            for (int nj = 0; nj < 4; nj++) {
                const int cl = wn + nj * 8 + 2 * t;
                const float bx = bias[bn + cl], by = bias[bn + cl + 1];
                const int r0 = wm + mi * 16 + g;
                Tt[cl * 136 + r0]       = __float2half_rn(acc[mi][nj][0] + bx);
                Tt[(cl + 1) * 136 + r0] = __float2half_rn(acc[mi][nj][1] + by);
                Tt[cl * 136 + r0 + 8]       = __float2half_rn(acc[mi][nj][2] + bx);
                Tt[(cl + 1) * 136 + r0 + 8] = __float2half_rn(acc[mi][nj][3] + by);
            }
        __syncthreads();
        const int bb = bm >> 12;           // batch
        const int tok0 = bm & (L_ - 1);
        // 128 d-cols x 128 tokens = 2048 float4 units (16 per d-col)
#pragma unroll
        for (int p = 0; p < 8; p++) {
            int i = tid + p * 256;
            int row = i >> 4, f4 = i & 15;
            const int gc = bn + row;
            const int hh = gc >> 6, dl = gc & 63;
            float4 v = *(float4*)&Tt[row * 136 + f4 * 8];
            *(float4*)&g_vt[((size_t)((bb * H_ + hh) * 64 + dl)) * L_ + tok0 + f4 * 8] = v;
        }
    } else {
        const float sc = (mode == 2) ? QSCALE : 1.f;
        __half* Cout = (mode == 2) ? g_qh : g_kh;
#pragma unroll
        for (int mi = 0; mi < 4; mi++)
#pragma unroll
            for (int nj = 0; nj < 4; nj++) {
                const int col = bn + wn + nj * 8 + 2 * t;
                const float bx = bias[col], by = bias[col + 1];
                const int r0 = bm + wm + mi * 16 + g;
                uint32_t v0 = h2pack((acc[mi][nj][0] + bx) * sc, (acc[mi][nj][1] + by) * sc);
                uint32_t v1 = h2pack((acc[mi][nj][2] + bx) * sc, (acc[mi][nj][3] + by) * sc);
                *(uint32_t*)&Cout[(size_t)r0 * D_ + col] = v0;
                *(uint32_t*)&Cout[(size_t)(r0 + 8) * D_ + col] = v1;
            }
    }
#undef ISSUE
}

__global__ __launch_bounds__(256, 2) void gemm_qkv_f16(
    const float* __restrict__ bq, const float* __restrict__ bk,
    const float* __restrict__ bv) {
    const __half* Wt = g_wh + (size_t)blockIdx.z * D_ * D_;
    const float* bias;
    int mode;
    if (blockIdx.z == 0)      { bias = bq; mode = 2; }
    else if (blockIdx.z == 1) { bias = bk; mode = 1; }
    else                      { bias = bv; mode = 3; }
    gemm_f16_body(g_xh, Wt, bias, nullptr, mode);
}

__global__ __launch_bounds__(256, 2) void gemm_out_f16(
    const float* __restrict__ bo, float* __restrict__ out) {
    gemm_f16_body(g_ah, g_wh + (size_t)3 * D_ * D_, bo, out, 0);
}

// ---------------------------------------------------------------------------
// Sliding-window flash attention, f16 mma + ldmatrix, 256 threads.
// Ks [key][d] stride 36 b32; Vt [d][token] stride 36 b32 (LDSM conflict-free).
// P: C-frag == A-frag in f16 -> zero shuffles.
// ---------------------------------------------------------------------------
#define AKSTR 36
#define ATTN_SMEM (2 * 2 * 64 * AKSTR * 4)   // 36864 B

__global__ __launch_bounds__(256) void attn_f16() {
    extern __shared__ float smem_f[];
    uint32_t* Ks = (uint32_t*)smem_f;           // [2][64][36]
    uint32_t* Vs = Ks + 2 * 64 * AKSTR;         // [2][64][36]
    const uint32_t sK = smem_u32(Ks), sV = smem_u32(Vs);

    const int tid  = threadIdx.x;
    const int lane = tid & 31;
    const int warp = tid >> 5;
    const int g = lane >> 2, t = lane & 3;
    const int qt = blockIdx.x;            // 0..3
    const int h  = blockIdx.y;
    const int b  = blockIdx.z >> 3;
    const int c  = blockIdx.z & 7;
    const int qrow0 = b * L_ + c * W_ + qt * 128 + warp * 16;

    // LDSM per-lane base offset (b32 units): rows n0-7/n8-15, k halves 0/8
    const int l8 = lane & 7;
    const uint32_t fOff = (uint32_t)((l8 + (lane >> 4) * 8) * AKSTR
                                     + ((lane >> 3) & 1) * 4);

    // Q a-frags (scale pre-folded into g_qh). b32 view: 512 per row.
    const uint32_t* q32 = (const uint32_t*)g_qh;
    uint32_t qf[4][4];
#pragma unroll
    for (int ks = 0; ks < 4; ks++) {
        const int cc = h * 32 + ks * 8 + t;
        qf[ks][0] = q32[(size_t)(qrow0 + g) * 512 + cc];
        qf[ks][1] = q32[(size_t)(qrow0 + g + 8) * 512 + cc];
        qf[ks][2] = q32[(size_t)(qrow0 + g) * 512 + cc + 4];
        qf[ks][3] = q32[(size_t)(qrow0 + g + 8) * 512 + cc + 4];
    }

    float of[8][4];
    float mrow[2] = { -1e30f, -1e30f }, lrow[2] = { 0.f, 0.f };
#pragma unroll
    for (int nj = 0; nj < 8; nj++)
#pragma unroll
        for (int e = 0; e < 4; e++) of[nj][e] = 0.f;

    const __half* kh = g_kh;
    const size_t vtbase = (size_t)(b * H_ + h) * 64 * L_;

    auto issueKV = [&](int kt, int buf) {
        const int tok = (c - 1) * W_ + kt * 64;
#pragma unroll
        for (int p = 0; p < 2; p++) {
            int s_ = tid + p * 256;
            int r_ = s_ >> 3, c4_ = s_ & 7;   // 8 x 16B per 64-wide f16 row
            uint32_t off = (uint32_t)((buf * 64 + r_) * AKSTR + c4_ * 4) * 4;
            cp_async16(sK + off, &kh[(size_t)(b * L_ + tok + r_) * D_ + h * 64 + c4_ * 8]);
            cp_async16(sV + off, &g_vt[vtbase + (size_t)r_ * L_ + tok + c4_ * 8]);
        }
    };

    const int kt0 = (c == 0) ? 8 : 0;   // chunk 0 lookback is padding
    issueKV(kt0, 0); CP_COMMIT();
    for (int kt = kt0; kt < 16; kt++) {
        const int buf = (kt - kt0) & 1;
        if (kt + 1 < 16) { issueKV(kt + 1, buf ^ 1); CP_COMMIT(); CP_WAIT(1); }
        else             { CP_WAIT(0); }
        __syncthreads();

        const uint32_t baseK = sK + (uint32_t)(buf * 64 * AKSTR) * 4;
        const uint32_t baseV = sV + (uint32_t)(buf * 64 * AKSTR) * 4;

        // S = Q @ K^T
        float s[8][4];
#pragma unroll
        for (int nj = 0; nj < 8; nj++)
#pragma unroll
            for (int e = 0; e < 4; e++) s[nj][e] = 0.f;
#pragma unroll
        for (int ks = 0; ks < 4; ks++) {
#pragma unroll
            for (int np = 0; np < 4; np++) {
                uint32_t bfp[4];
                ldsm4(bfp, baseK + (fOff + np * 16 * AKSTR + ks * 8) * 4);
                mma16(s[np * 2],     qf[ks], &bfp[0]);
                mma16(s[np * 2 + 1], qf[ks], &bfp[2]);
            }
        }

        // Online softmax (base-2; row = quad of 4 lanes)
#pragma unroll
        for (int hh = 0; hh < 2; hh++) {
            const int e0 = hh * 2;
            float mx = -1e30f;
#pragma unroll
            for (int nj = 0; nj < 8; nj++)
                mx = fmaxf(mx, fmaxf(s[nj][e0], s[nj][e0 + 1]));
            mx = fmaxf(mx, __shfl_xor_sync(0xffffffffu, mx, 1));
            mx = fmaxf(mx, __shfl_xor_sync(0xffffffffu, mx, 2));
            const float mnew = fmaxf(mrow[hh], mx);
            const float corr = ex2(mrow[hh] - mnew);
            float rs = 0.f;
#pragma unroll
            for (int nj = 0; nj < 8; nj++) {
                float p0 = ex2(s[nj][e0] - mnew);
                float p1 = ex2(s[nj][e0 + 1] - mnew);
                s[nj][e0] = p0; s[nj][e0 + 1] = p1;
                rs += p0 + p1;
                of[nj][e0] *= corr;
                of[nj][e0 + 1] *= corr;
            }
            rs += __shfl_xor_sync(0xffffffffu, rs, 1);
            rs += __shfl_xor_sync(0xffffffffu, rs, 2);
            lrow[hh] = lrow[hh] * corr + rs;
            mrow[hh] = mnew;
        }

        // O += P @ V: pack adjacent S tiles into f16 A-frags (no shuffles)
#pragma unroll
        for (int kk = 0; kk < 4; kk++) {
            uint32_t am[4];
            am[0] = h2pack(s[2 * kk][0], s[2 * kk][1]);
            am[1] = h2pack(s[2 * kk][2], s[2 * kk][3]);
            am[2] = h2pack(s[2 * kk + 1][0], s[2 * kk + 1][1]);
            am[3] = h2pack(s[2 * kk + 1][2], s[2 * kk + 1][3]);
#pragma unroll
            for (int np = 0; np < 4; np++) {
                uint32_t bfp[4];
                ldsm4(bfp, baseV + (fOff + np * 16 * AKSTR + kk * 8) * 4);
                mma16(of[np * 2],     am, &bfp[0]);
                mma16(of[np * 2 + 1], am, &bfp[2]);
            }
        }
        __syncthreads();
    }

    // Epilogue: normalize, f16 store to g_ah
    const float inv0 = 1.f / lrow[0];
    const float inv1 = 1.f / lrow[1];
#pragma unroll
    for (int nj = 0; nj < 8; nj++) {
        const int col = h * 64 + nj * 8 + 2 * t;
        uint32_t v0 = h2pack(of[nj][0] * inv0, of[nj][1] * inv0);
        uint32_t v1 = h2pack(of[nj][2] * inv1, of[nj][3] * inv1);
        *(uint32_t*)&g_ah[(size_t)(qrow0 + g) * D_ + col] = v0;
        *(uint32_t*)&g_ah[(size_t)(qrow0 + g + 8) * D_ + col] = v1;
    }
}

// ---------------------------------------------------------------------------
extern "C" void kernel_launch(void* const* d_in, const int* in_sizes, int n_in,
                              void* d_out, int out_size) {
    const float* x  = (const float*)d_in[0];
    const float* Wq = (const float*)d_in[1];
    const float* bq = (const float*)d_in[2];
    const float* Wk = (const float*)d_in[3];
    const float* bk = (const float*)d_in[4];
    const float* Wv = (const float*)d_in[5];
    const float* bv = (const float*)d_in[6];
    const float* Wo = (const float*)d_in[7];
    const float* bo = (const float*)d_in[8];
    float* out = (float*)d_out;

    cudaFuncSetAttribute(gemm_qkv_f16, cudaFuncAttributeMaxDynamicSharedMemorySize, GEMM_SMEM);
    cudaFuncSetAttribute(gemm_out_f16, cudaFuncAttributeMaxDynamicSharedMemorySize, GEMM_SMEM);
    cudaFuncSetAttribute(attn_f16, cudaFuncAttributeMaxDynamicSharedMemorySize, ATTN_SMEM);

    cvt_all<<<1024, 256>>>(x, Wq, Wk, Wv, Wo);
    gemm_qkv_f16<<<dim3(D_ / 128, M_ / 128, 3), 256, GEMM_SMEM>>>(bq, bk, bv);
    attn_f16<<<dim3(4, H_, B_ * C_), 256, ATTN_SMEM>>>();
    gemm_out_f16<<<dim3(D_ / 128, M_ / 128), 256, GEMM_SMEM>>>(bo, out);
}